// round 8
// baseline (speedup 1.0000x reference)
#include <cuda_runtime.h>
#include <math.h>
#include <stdint.h>

#define S 1024
#define SS (S*S)
#define NBH 4096
#define CAP 512
#define TARGETN 384u
#define MAXR 256
#define NKP 17
#define HOTCAP 8192
#define NW 16               // CAP/32 bitset words
#define FULL 0xFFFFFFFFu

#define HOTB  0x3F733333u   // __float_as_uint(0.95f)
#define HRNG  (0x3F800000u - 0x3F733333u)

// ---------------- scratch (static __device__, zero at module load) ----------
__device__ unsigned int       g_hist[NBH];
__device__ unsigned int       g_cnt_hot;
__device__ unsigned long long g_hot[HOTCAP];   // hot candidates (bits<<32 | ~idx)
__device__ float2             g_pos[CAP];      // sorted candidate positions
__device__ unsigned int       g_m;             // number of valid sorted candidates
__device__ int                g_selx[MAXR], g_sely[MAXR];
__device__ int                g_nsel;

static __device__ __forceinline__ unsigned bucket_hot(unsigned bits) {
    unsigned d = bits - HOTB;
    unsigned b = (unsigned)(((unsigned long long)d * NBH) / HRNG);
    return b >= NBH ? (NBH - 1) : b;
}

// ---------------- K1: scan heatmap; keep only conf>=0.95 candidates ---------
__global__ void __launch_bounds__(512) k_scan(const float* __restrict__ x) {
    const float4* __restrict__ x4 = (const float4*)x;
    int i = blockIdx.x * blockDim.x + threadIdx.x;   // exactly SS/4 threads
    int lane = threadIdx.x & 31;

    float4 v4 = x4[i];
    float vs[4] = {v4.x, v4.y, v4.z, v4.w};
    unsigned long long keys[4];
    unsigned bbits[4];
    int cnt = 0;
    #pragma unroll
    for (int c = 0; c < 4; c++) {
        float v = vs[c];
        if (v > 2.9f) {  // prefilter; exact test on conf bits below
            float conf = 1.0f / (1.0f + expf(-v));   // same formula as reference
            unsigned bits = __float_as_uint(conf);
            if (bits >= HOTB) {
                int idx = 4 * i + c;
                keys[cnt]  = ((unsigned long long)bits << 32) | (unsigned)(~idx);
                bbits[cnt] = bits;
                cnt++;
            }
        }
    }
    unsigned pre = (unsigned)cnt;
    #pragma unroll
    for (int off = 1; off < 32; off <<= 1) {
        unsigned v = __shfl_up_sync(FULL, pre, off);
        if (lane >= off) pre += v;
    }
    unsigned total = __shfl_sync(FULL, pre, 31);
    if (total) {
        unsigned base = 0;
        if (lane == 31) base = atomicAdd(&g_cnt_hot, total);
        base = __shfl_sync(FULL, base, 31);
        unsigned mybase = base + pre - (unsigned)cnt;
        for (int c = 0; c < cnt; c++) {
            unsigned p = mybase + c;
            if (p < HOTCAP) g_hot[p] = keys[c];
            atomicAdd(&g_hist[bucket_hot(bbits[c])], 1u);   // RED
        }
    }
}

// ---------------- K2: cutoff + collect + register bitonic sort --------------
__global__ void __launch_bounds__(1024, 1) k_top() {
    __shared__ unsigned long long sk[CAP];
    __shared__ unsigned cs[1024];
    __shared__ unsigned seg_suf[32];
    __shared__ unsigned s_cut;
    __shared__ unsigned s_cnt;

    int t = threadIdx.x;
    int lane = t & 31;

    // --- phase A: per-4-bucket partial sums + init ---
    {
        unsigned s = 0;
        #pragma unroll
        for (int b = 0; b < 4; b++) s += g_hist[t * 4 + b];
        cs[t] = s;
        if (t == 0) s_cnt = 0u;
        if (t < CAP) sk[t] = 0ULL;
    }
    __syncthreads();

    // --- phase B: parallel cutoff; strictly above boundary bucket ---
    if (t < 32) {
        unsigned a = 0;
        #pragma unroll
        for (int b = 0; b < 32; b++) a += cs[lane * 32 + b];
        unsigned suf = a;
        #pragma unroll
        for (int off = 1; off < 32; off <<= 1) {
            unsigned v = __shfl_down_sync(FULL, suf, off);
            if (lane + off < 32) suf += v;
        }
        seg_suf[lane] = suf;
        __syncwarp(FULL);
        unsigned bal = __ballot_sync(FULL, suf >= TARGETN);
        if (lane == 0) {
            if (bal == 0u) { s_cut = 0u; }  // total hot < TARGETN: keep all
            else {
                int lseg = 31 - __clz(bal);
                unsigned base = (lseg < 31) ? seg_suf[lseg + 1] : 0u;
                unsigned cum = base;
                int ccut = lseg * 32;
                for (int c = lseg * 32 + 31; c >= lseg * 32; c--) {
                    cum += cs[c];
                    if (cum >= TARGETN) { ccut = c; break; }
                }
                unsigned cc = cum - cs[ccut];
                unsigned h[4];
                #pragma unroll
                for (int b = 0; b < 4; b++) h[b] = g_hist[ccut * 4 + b];
                int bcut = ccut * 4;
                #pragma unroll
                for (int b = 3; b >= 0; b--) {
                    cc += h[b];
                    if (cc >= TARGETN) { bcut = ccut * 4 + b; break; }
                }
                s_cut = (unsigned)bcut + 1u;  // strict-above => count < TARGETN
            }
        }
    }
    __syncthreads();

    // --- phase C: collect above cutoff (warp-aggregated smem append) --------
    {
        unsigned n = min(g_cnt_hot, (unsigned)HOTCAP);
        unsigned cut = s_cut;
        unsigned rounds = (n + 1023u) / 1024u;
        for (unsigned r = 0; r < rounds; r++) {
            unsigned i = r * 1024u + (unsigned)t;
            bool keep = false;
            unsigned long long key = 0ULL;
            if (i < n) {
                key = g_hot[i];
                keep = bucket_hot((unsigned)(key >> 32)) >= cut;
            }
            unsigned bal = __ballot_sync(FULL, keep);
            if (bal) {
                unsigned wcnt = __popc(bal);
                unsigned base = 0;
                if (lane == 0) base = atomicAdd(&s_cnt, wcnt);
                base = __shfl_sync(FULL, base, 0);
                if (keep) {
                    unsigned p = base + __popc(bal & ((1u << lane) - 1u));
                    if (p < CAP) sk[p] = key;
                }
            }
        }
    }
    __syncthreads();

    // --- phase D: register bitonic sort, descending (1 key/thread) ----------
    unsigned long long key = (t < CAP) ? sk[t] : 0ULL;
    for (int k = 2; k <= CAP; k <<= 1) {
        for (int j = k >> 1; j > 0; j >>= 1) {
            unsigned long long other;
            if (j >= 32) {
                if (t < CAP) sk[t] = key;
                __syncthreads();
                other = (t < CAP) ? sk[t ^ j] : key;
                __syncthreads();
            } else {
                other = __shfl_xor_sync(FULL, key, j);
            }
            bool keepMax = (((t & j) == 0) == ((t & k) == 0));
            if (keepMax ? (other > key) : (other < key)) key = other;
        }
    }
    if (t < CAP) {
        unsigned idx = ~(unsigned)key;
        g_pos[t] = make_float2((float)(idx & (S - 1)), (float)(idx >> 10));
    }
    if (t == 0) g_m = min(s_cnt, (unsigned)CAP);
}

// ---------------- K3: conflict matrix + lexicographic MIS + cleanup ---------
__global__ void __launch_bounds__(1024, 1) k_mis() {
    __shared__ float2  pos[CAP];
    __shared__ unsigned s_mtx[CAP][NW];
    __shared__ unsigned s_accw[NW];

    int t = threadIdx.x;
    int lane = t & 31;

    if (t < CAP) pos[t] = g_pos[t];
    unsigned m = g_m;
    __syncthreads();

    // --- E1: triangular conflict matrix (thread pair t / t+CAP by parity) ---
    {
        int i   = (t < CAP) ? t : t - CAP;
        int par = (t < CAP) ? 0 : 1;
        if (i < (int)m) {
            float2 p = pos[i];
            int wi = i >> 5;
            int li = i & 31;
            for (int w = par; w <= wi; w += 2) {
                int jmax = (w == wi) ? li : 32;
                unsigned mw = 0u;
                for (int l = 0; l < jmax; l++) {
                    float2 q = pos[w * 32 + l];   // broadcast LDS
                    float dx = p.x - q.x, dy = p.y - q.y;
                    if (dx * dx + dy * dy <= 100.0f) mw |= 1u << l;
                }
                s_mtx[i][w] = mw;
            }
        }
    }
    __syncthreads();

    // --- E2: word-serial MIS on warp 0, ballot-per-leader elimination -------
    if (t < 32) {
        unsigned accw[NW];
        #pragma unroll
        for (int w = 0; w < NW; w++) accw[w] = 0u;
        int nwords = ((int)m + 31) >> 5;
        for (int w = 0; w < nwords; w++) {
            int i = w * 32 + lane;
            bool valid = (i < (int)m);
            unsigned rej = 0u;
            for (int v = 0; v < w; v++)
                rej |= (valid ? s_mtx[i][v] : 0u) & accw[v];
            unsigned mlow = valid ? s_mtx[i][w] : 0u;   // conflicts with lower lanes
            unsigned cand = __ballot_sync(FULL, valid && rej == 0u);
            unsigned acc = 0u;
            while (cand) {
                int c = __ffs(cand) - 1;
                acc |= 1u << c;
                unsigned kill = __ballot_sync(FULL, (mlow >> c) & 1u);
                cand &= ~(kill | (1u << c));
            }
            accw[w] = acc;            // uniform across warp (ballot result)
        }
        if (lane < NW) s_accw[lane] = accw[lane];
    }
    __syncthreads();

    // --- extract accepted in rank order, cap MAXR ---
    if (t < (int)m) {
        unsigned aw = s_accw[t >> 5];
        if ((aw >> lane) & 1u) {
            int below = 0;
            int wi = t >> 5;
            for (int w = 0; w < wi; w++) below += __popc(s_accw[w]);
            below += __popc(aw & ((1u << lane) - 1u));
            if (below < MAXR) {
                float2 p = pos[t];
                g_selx[below] = (int)p.x;
                g_sely[below] = (int)p.y;
            }
        }
    }
    if (t == 0) {
        int tot = 0;
        #pragma unroll
        for (int w = 0; w < NW; w++) tot += __popc(s_accw[w]);
        g_nsel = min(tot, MAXR);
    }

    // --- cleanup for next graph replay (hist + counter) ---
    #pragma unroll
    for (int b = 0; b < NBH / 1024; b++) g_hist[b * 1024 + t] = 0u;
    if (t == 0) g_cnt_hot = 0u;
}

// ---------------- K4: gather displacements, emit outputs --------------------
// out layout (9472 f32): root[256][2] | kp[256][17][2] | valid[256]
__global__ void __launch_bounds__(1024) k_emit(const float* __restrict__ x,
                                               float* __restrict__ out) {
    int t = threadIdx.x;
    int ns = g_nsel;
    const float Z = 1.41421356237309515f * 1024.0f;  // sqrt(2)*S

    if (blockIdx.x == 0 && t < MAXR) {
        int r = t;
        bool v = (r < ns);
        float fx = v ? (float)g_selx[r] : 0.0f;
        float fy = v ? (float)g_sely[r] : 0.0f;
        out[2 * r]     = fx * 4.0f;
        out[2 * r + 1] = fy * 4.0f;
        out[2 * MAXR + MAXR * 2 * NKP + r] = v ? 1.0f : 0.0f;
    }

    int j = blockIdx.x * 1024 + t;
    if (j < MAXR * NKP) {
        int r = j / NKP, kpi = j - r * NKP;
        float kx = 0.0f, ky = 0.0f;
        if (r < ns) {
            int xi = g_selx[r], yi = g_sely[r];
            int off = yi * S + xi;
            float dx = tanhf(x[(1 + 2 * kpi) * SS + off]);
            float dy = tanhf(x[(2 + 2 * kpi) * SS + off]);
            float ddx = dx * Z, ddy = dy * Z;
            kx = ddx + (float)xi;
            ky = ddy + (float)yi;
            float d = sqrtf(ddx * ddx + ddy * ddy);
            if (d < 2.0f) { kx = 0.0f; ky = 0.0f; }
            kx *= 4.0f; ky *= 4.0f;
        }
        out[2 * MAXR + 2 * j]     = kx;
        out[2 * MAXR + 2 * j + 1] = ky;
    }
}

// ---------------- entry ----------------
extern "C" void kernel_launch(void* const* d_in, const int* in_sizes, int n_in,
                              void* d_out, int out_size) {
    const float* x = (const float*)d_in[0];
    float* out = (float*)d_out;
    (void)in_sizes; (void)n_in; (void)out_size;

    k_scan<<<SS / 4 / 512, 512>>>(x);
    k_top<<<1, 1024>>>();
    k_mis<<<1, 1024>>>();
    k_emit<<<(MAXR * NKP + 1023) / 1024, 1024>>>(x, out);
}

// round 9
// speedup vs baseline: 1.5467x; 1.5467x over previous
#include <cuda_runtime.h>
#include <math.h>
#include <stdint.h>

#define S 1024
#define SS (S*S)
#define NBH 4096
#define CAP 512
#define TARGETN 384u
#define MAXR 256
#define NKP 17
#define HOTCAP 8192
#define NW2 12              // 384/32 bitset words for MIS
#define FULL 0xFFFFFFFFu

#define HOTB  0x3F733333u   // __float_as_uint(0.95f)
#define HRNG  (0x3F800000u - 0x3F733333u)

// ---------------- scratch (static __device__, zero at module load) ----------
__device__ unsigned int       g_hist[NBH];
__device__ unsigned int       g_cnt_hot;
__device__ unsigned long long g_hot[HOTCAP];   // hot candidates (bits<<32 | ~idx)

static __device__ __forceinline__ unsigned bucket_hot(unsigned bits) {
    unsigned d = bits - HOTB;
    unsigned b = (unsigned)(((unsigned long long)d * NBH) / HRNG);
    return b >= NBH ? (NBH - 1) : b;
}

// ---------------- K1: scan heatmap; keep only conf>=0.95 candidates ---------
__global__ void __launch_bounds__(512) k_scan(const float* __restrict__ x) {
    const float4* __restrict__ x4 = (const float4*)x;
    int i = blockIdx.x * blockDim.x + threadIdx.x;   // exactly SS/4 threads
    int lane = threadIdx.x & 31;

    float4 v4 = x4[i];
    float vs[4] = {v4.x, v4.y, v4.z, v4.w};
    unsigned long long keys[4];
    unsigned bbits[4];
    int cnt = 0;
    #pragma unroll
    for (int c = 0; c < 4; c++) {
        float v = vs[c];
        if (v > 2.9f) {  // prefilter; exact test on conf bits below
            float conf = 1.0f / (1.0f + expf(-v));   // same formula as reference
            unsigned bits = __float_as_uint(conf);
            if (bits >= HOTB) {
                int idx = 4 * i + c;
                keys[cnt]  = ((unsigned long long)bits << 32) | (unsigned)(~idx);
                bbits[cnt] = bits;
                cnt++;
            }
        }
    }
    unsigned pre = (unsigned)cnt;
    #pragma unroll
    for (int off = 1; off < 32; off <<= 1) {
        unsigned v = __shfl_up_sync(FULL, pre, off);
        if (lane >= off) pre += v;
    }
    unsigned total = __shfl_sync(FULL, pre, 31);
    if (total) {
        unsigned base = 0;
        if (lane == 31) base = atomicAdd(&g_cnt_hot, total);
        base = __shfl_sync(FULL, base, 31);
        unsigned mybase = base + pre - (unsigned)cnt;
        for (int c = 0; c < cnt; c++) {
            unsigned p = mybase + c;
            if (p < HOTCAP) g_hot[p] = keys[c];
            atomicAdd(&g_hist[bucket_hot(bbits[c])], 1u);   // RED
        }
    }
}

// ---------------- K2: cutoff + collect + reg-sort + relax-MIS + emit --------
__global__ void __launch_bounds__(1024, 1) k_mid(const float* __restrict__ x,
                                                 float* __restrict__ out) {
    __shared__ unsigned long long sk[CAP];    // 4 KB (collect + sort exchange)
    __shared__ float2  pos[CAP];              // 4 KB
    __shared__ unsigned cs[1024];
    __shared__ unsigned seg_suf[32];
    __shared__ unsigned s_cut;
    __shared__ unsigned s_cnt;
    __shared__ unsigned s_und[NW2], s_acc[NW2];
    __shared__ int s_flag;
    __shared__ int s_selx[MAXR], s_sely[MAXR];
    __shared__ int s_nsel;

    int t = threadIdx.x;
    int lane = t & 31;

    // --- phase A: per-4-bucket partial sums + init ---
    {
        unsigned s = 0;
        #pragma unroll
        for (int b = 0; b < 4; b++) s += g_hist[t * 4 + b];
        cs[t] = s;
        if (t == 0) s_cnt = 0u;
        if (t < CAP) sk[t] = 0ULL;
    }
    __syncthreads();

    // --- phase B: parallel cutoff; strictly above boundary bucket ---
    if (t < 32) {
        unsigned a = 0;
        #pragma unroll
        for (int b = 0; b < 32; b++) a += cs[lane * 32 + b];
        unsigned suf = a;
        #pragma unroll
        for (int off = 1; off < 32; off <<= 1) {
            unsigned v = __shfl_down_sync(FULL, suf, off);
            if (lane + off < 32) suf += v;
        }
        seg_suf[lane] = suf;
        __syncwarp(FULL);
        unsigned bal = __ballot_sync(FULL, suf >= TARGETN);
        if (lane == 0) {
            if (bal == 0u) { s_cut = 0u; }  // total hot < TARGETN: keep all (<384)
            else {
                int lseg = 31 - __clz(bal);
                unsigned base = (lseg < 31) ? seg_suf[lseg + 1] : 0u;
                unsigned cum = base;
                int ccut = lseg * 32;
                for (int c = lseg * 32 + 31; c >= lseg * 32; c--) {
                    cum += cs[c];
                    if (cum >= TARGETN) { ccut = c; break; }
                }
                unsigned cc = cum - cs[ccut];
                unsigned h[4];
                #pragma unroll
                for (int b = 0; b < 4; b++) h[b] = g_hist[ccut * 4 + b];
                int bcut = ccut * 4;
                #pragma unroll
                for (int b = 3; b >= 0; b--) {
                    cc += h[b];
                    if (cc >= TARGETN) { bcut = ccut * 4 + b; break; }
                }
                s_cut = (unsigned)bcut + 1u;  // strict-above => count < TARGETN
            }
        }
    }
    __syncthreads();

    // --- phase C: collect above cutoff (warp-aggregated smem append) --------
    {
        unsigned n = min(g_cnt_hot, (unsigned)HOTCAP);
        unsigned cut = s_cut;
        unsigned rounds = (n + 1023u) / 1024u;
        for (unsigned r = 0; r < rounds; r++) {
            unsigned i = r * 1024u + (unsigned)t;
            bool keep = false;
            unsigned long long key = 0ULL;
            if (i < n) {
                key = g_hot[i];
                keep = bucket_hot((unsigned)(key >> 32)) >= cut;
            }
            unsigned bal = __ballot_sync(FULL, keep);
            if (bal) {
                unsigned wcnt = __popc(bal);
                unsigned base = 0;
                if (lane == 0) base = atomicAdd(&s_cnt, wcnt);
                base = __shfl_sync(FULL, base, 0);
                if (keep) {
                    unsigned p = base + __popc(bal & ((1u << lane) - 1u));
                    if (p < CAP) sk[p] = key;
                }
            }
        }
    }
    __syncthreads();

    // --- phase D: register bitonic sort, descending (1 key/thread, t<512) ---
    unsigned long long key = (t < CAP) ? sk[t] : 0ULL;
    for (int k = 2; k <= CAP; k <<= 1) {
        for (int j = k >> 1; j > 0; j >>= 1) {
            unsigned long long other;
            if (j >= 32) {
                if (t < CAP) sk[t] = key;
                __syncthreads();
                other = (t < CAP) ? sk[t ^ j] : key;
                __syncthreads();
            } else {
                other = __shfl_xor_sync(FULL, key, j);
            }
            bool keepMax = (((t & j) == 0) == ((t & k) == 0));
            if (keepMax ? (other > key) : (other < key)) key = other;
        }
    }
    unsigned m = min(s_cnt, (unsigned)CAP);   // m < 384 guaranteed
    if (t < CAP) {
        unsigned idx = ~(unsigned)key;
        pos[t] = make_float2((float)(idx & (S - 1)), (float)(idx >> 10));
    }
    // init MIS state
    {
        unsigned alive = __ballot_sync(FULL, t < (int)m);
        if (t < NW2 * 32 && lane == 0) { s_und[t >> 5] = alive; s_acc[t >> 5] = 0u; }
        if (t == 0) s_flag = 1;
    }
    __syncthreads();

    // --- phase E: block-parallel lexicographic MIS (== greedy NMS) ----------
    float2 myp = (t < (int)m) ? pos[t] : make_float2(0.f, 0.f);
    int wi = t >> 5;                    // my word index
    unsigned msk[NW2];
    #pragma unroll
    for (int w = 0; w < NW2; w++) msk[w] = 0u;
    if (t < (int)m) {
        #pragma unroll
        for (int w = 0; w < NW2; w++) {
            if (w <= wi) {
                unsigned mw = 0u;
                int jmax = min(32, t - w * 32);
                for (int l = 0; l < jmax; l++) {
                    float2 q = pos[w * 32 + l];   // broadcast LDS
                    float dx = myp.x - q.x, dy = myp.y - q.y;
                    if (dx * dx + dy * dy <= 100.0f) mw |= 1u << l;
                }
                msk[w] = mw;
            }
        }
    }
    bool undec = (t < (int)m);
    bool isacc = false;

    for (int round = 0; round < 384; round++) {
        unsigned u[NW2], a[NW2];
        #pragma unroll
        for (int w = 0; w < NW2; w++) {
            if (w <= wi && w < NW2) { u[w] = s_und[w]; a[w] = s_acc[w]; }
            else { u[w] = 0u; a[w] = 0u; }
        }
        __syncthreads();
        if (t == 0) s_flag = 0;
        if (undec) {
            unsigned pend = 0u, accc = 0u;
            #pragma unroll
            for (int w = 0; w < NW2; w++) { pend |= msk[w] & u[w]; accc |= msk[w] & a[w]; }
            if (pend == 0u) { undec = false; isacc = (accc == 0u); }
        }
        __syncthreads();
        unsigned uw = __ballot_sync(FULL, undec);
        unsigned aw = __ballot_sync(FULL, isacc);
        if (t < NW2 * 32 && lane == 0) {
            s_und[t >> 5] = uw;
            s_acc[t >> 5] = aw;
            if (uw) s_flag = 1;
        }
        __syncthreads();
        if (!s_flag) break;
        __syncthreads();
    }

    // --- extract accepted in rank order, cap MAXR ---
    if (t < (int)m && isacc) {
        int below = 0;
        #pragma unroll
        for (int w = 0; w < NW2; w++) if (w < wi) below += __popc(s_acc[w]);
        below += __popc(s_acc[wi] & ((1u << lane) - 1u));
        if (below < MAXR) { s_selx[below] = (int)myp.x; s_sely[below] = (int)myp.y; }
    }
    if (t == 0) {
        int tot = 0;
        #pragma unroll
        for (int w = 0; w < NW2; w++) tot += __popc(s_acc[w]);
        s_nsel = min(tot, MAXR);
    }
    __syncthreads();

    // --- phase F: emit outputs (batched scattered loads for MLP) ------------
    // out layout (9472 f32): root[256][2] | kp[256][17][2] | valid[256]
    {
        int ns = s_nsel;
        const float Z = 1.41421356237309515f * 1024.0f;  // sqrt(2)*S
        if (t < MAXR) {
            int r = t;
            bool v = (r < ns);
            float fx = v ? (float)s_selx[r] : 0.0f;
            float fy = v ? (float)s_sely[r] : 0.0f;
            out[2 * r]     = fx * 4.0f;
            out[2 * r + 1] = fy * 4.0f;
            out[2 * MAXR + MAXR * 2 * NKP + r] = v ? 1.0f : 0.0f;
        }
        // gather all displacement pairs first (independent LDGs -> one wave)
        float rdx[5], rdy[5];
        int   rr[5], xi5[5], yi5[5];
        bool  act[5];
        #pragma unroll
        for (int it = 0; it < 5; it++) {
            int j = t + it * 1024;
            act[it] = false;
            if (j < MAXR * NKP) {
                int r = j / NKP, kpi = j - r * NKP;
                rr[it] = r;
                if (r < ns) {
                    int xi = s_selx[r], yi = s_sely[r];
                    xi5[it] = xi; yi5[it] = yi;
                    int off = yi * S + xi;
                    rdx[it] = x[(1 + 2 * kpi) * SS + off];
                    rdy[it] = x[(2 + 2 * kpi) * SS + off];
                    act[it] = true;
                }
            }
        }
        #pragma unroll
        for (int it = 0; it < 5; it++) {
            int j = t + it * 1024;
            if (j < MAXR * NKP) {
                float kx = 0.0f, ky = 0.0f;
                if (act[it]) {
                    float ddx = tanhf(rdx[it]) * Z, ddy = tanhf(rdy[it]) * Z;
                    kx = ddx + (float)xi5[it];
                    ky = ddy + (float)yi5[it];
                    float d = sqrtf(ddx * ddx + ddy * ddy);
                    if (d < 2.0f) { kx = 0.0f; ky = 0.0f; }
                    kx *= 4.0f; ky *= 4.0f;
                }
                out[2 * MAXR + 2 * j]     = kx;
                out[2 * MAXR + 2 * j + 1] = ky;
            }
        }
    }

    // --- phase G: cleanup for next graph replay ---
    #pragma unroll
    for (int b = 0; b < NBH / 1024; b++) g_hist[b * 1024 + t] = 0u;
    if (t == 0) g_cnt_hot = 0u;
}

// ---------------- entry ----------------
extern "C" void kernel_launch(void* const* d_in, const int* in_sizes, int n_in,
                              void* d_out, int out_size) {
    const float* x = (const float*)d_in[0];
    float* out = (float*)d_out;
    (void)in_sizes; (void)n_in; (void)out_size;

    k_scan<<<SS / 4 / 512, 512>>>(x);
    k_mid<<<1, 1024>>>(x, out);
}

// round 10
// speedup vs baseline: 1.7832x; 1.1529x over previous
#include <cuda_runtime.h>
#include <math.h>
#include <stdint.h>

#define S 1024
#define SS (S*S)
#define NBH 4096
#define CAP 512
#define TARGETN 384u
#define MAXR 256
#define NKP 17
#define HOTCAP 8192
#define NW2 12              // 384/32 bitset words for MIS
#define MPAD 13             // padded row stride (bank-conflict-free)
#define FULL 0xFFFFFFFFu

#define HOTB  0x3F733333u   // __float_as_uint(0.95f)
#define HRNG  (0x3F800000u - 0x3F733333u)

// ---------------- scratch (static __device__, zero at module load) ----------
__device__ unsigned int       g_hist[NBH];
__device__ unsigned int       g_cnt_hot;
__device__ unsigned long long g_hot[HOTCAP];   // hot candidates (bits<<32 | ~idx)
__device__ int                g_selx[MAXR], g_sely[MAXR];
__device__ int                g_nsel;

static __device__ __forceinline__ unsigned bucket_hot(unsigned bits) {
    unsigned d = bits - HOTB;
    unsigned b = (unsigned)(((unsigned long long)d * NBH) / HRNG);
    return b >= NBH ? (NBH - 1) : b;
}

// ---------------- K1: scan heatmap; keep only conf>=0.95 candidates ---------
__global__ void __launch_bounds__(512) k_scan(const float* __restrict__ x) {
    const float4* __restrict__ x4 = (const float4*)x;
    int i = blockIdx.x * blockDim.x + threadIdx.x;   // exactly SS/4 threads
    int lane = threadIdx.x & 31;

    float4 v4 = x4[i];
    float vs[4] = {v4.x, v4.y, v4.z, v4.w};
    unsigned long long keys[4];
    unsigned bbits[4];
    int cnt = 0;
    #pragma unroll
    for (int c = 0; c < 4; c++) {
        float v = vs[c];
        if (v > 2.9f) {  // prefilter; exact test on conf bits below
            float conf = 1.0f / (1.0f + expf(-v));   // same formula as reference
            unsigned bits = __float_as_uint(conf);
            if (bits >= HOTB) {
                int idx = 4 * i + c;
                keys[cnt]  = ((unsigned long long)bits << 32) | (unsigned)(~idx);
                bbits[cnt] = bits;
                cnt++;
            }
        }
    }
    unsigned pre = (unsigned)cnt;
    #pragma unroll
    for (int off = 1; off < 32; off <<= 1) {
        unsigned v = __shfl_up_sync(FULL, pre, off);
        if (lane >= off) pre += v;
    }
    unsigned total = __shfl_sync(FULL, pre, 31);
    if (total) {
        unsigned base = 0;
        if (lane == 31) base = atomicAdd(&g_cnt_hot, total);
        base = __shfl_sync(FULL, base, 31);
        unsigned mybase = base + pre - (unsigned)cnt;
        for (int c = 0; c < cnt; c++) {
            unsigned p = mybase + c;
            if (p < HOTCAP) g_hot[p] = keys[c];
            atomicAdd(&g_hist[bucket_hot(bbits[c])], 1u);   // RED
        }
    }
}

// ---------------- K2: cutoff + collect + reg-sort + split-build + relax-MIS -
__global__ void __launch_bounds__(1024, 1) k_mid() {
    __shared__ unsigned long long sk[CAP];          // 4 KB
    __shared__ float2  pos[CAP];                    // 4 KB
    __shared__ unsigned s_mtx[384 * MPAD];          // ~19.5 KB conflict matrix
    __shared__ unsigned cs[1024];
    __shared__ unsigned seg_suf[32];
    __shared__ unsigned s_cut;
    __shared__ unsigned s_cnt;
    __shared__ unsigned s_und[NW2], s_acc[NW2];
    __shared__ int s_flag;

    int t = threadIdx.x;
    int lane = t & 31;

    // --- phase A: per-4-bucket partial sums + init ---
    {
        unsigned s = 0;
        #pragma unroll
        for (int b = 0; b < 4; b++) s += g_hist[t * 4 + b];
        cs[t] = s;
        if (t == 0) s_cnt = 0u;
        if (t < CAP) sk[t] = 0ULL;
    }
    __syncthreads();

    // --- phase B: parallel cutoff; strictly above boundary bucket ---
    if (t < 32) {
        unsigned a = 0;
        #pragma unroll
        for (int b = 0; b < 32; b++) a += cs[lane * 32 + b];
        unsigned suf = a;
        #pragma unroll
        for (int off = 1; off < 32; off <<= 1) {
            unsigned v = __shfl_down_sync(FULL, suf, off);
            if (lane + off < 32) suf += v;
        }
        seg_suf[lane] = suf;
        __syncwarp(FULL);
        unsigned bal = __ballot_sync(FULL, suf >= TARGETN);
        if (lane == 0) {
            if (bal == 0u) { s_cut = 0u; }  // total hot < TARGETN: keep all (<384)
            else {
                int lseg = 31 - __clz(bal);
                unsigned base = (lseg < 31) ? seg_suf[lseg + 1] : 0u;
                unsigned cum = base;
                int ccut = lseg * 32;
                for (int c = lseg * 32 + 31; c >= lseg * 32; c--) {
                    cum += cs[c];
                    if (cum >= TARGETN) { ccut = c; break; }
                }
                unsigned cc = cum - cs[ccut];
                unsigned h[4];
                #pragma unroll
                for (int b = 0; b < 4; b++) h[b] = g_hist[ccut * 4 + b];
                int bcut = ccut * 4;
                #pragma unroll
                for (int b = 3; b >= 0; b--) {
                    cc += h[b];
                    if (cc >= TARGETN) { bcut = ccut * 4 + b; break; }
                }
                s_cut = (unsigned)bcut + 1u;  // strict-above => count < TARGETN
            }
        }
    }
    __syncthreads();

    // --- phase C: collect above cutoff (warp-aggregated smem append) --------
    {
        unsigned n = min(g_cnt_hot, (unsigned)HOTCAP);
        unsigned cut = s_cut;
        unsigned rounds = (n + 1023u) / 1024u;
        for (unsigned r = 0; r < rounds; r++) {
            unsigned i = r * 1024u + (unsigned)t;
            bool keep = false;
            unsigned long long key = 0ULL;
            if (i < n) {
                key = g_hot[i];
                keep = bucket_hot((unsigned)(key >> 32)) >= cut;
            }
            unsigned bal = __ballot_sync(FULL, keep);
            if (bal) {
                unsigned wcnt = __popc(bal);
                unsigned base = 0;
                if (lane == 0) base = atomicAdd(&s_cnt, wcnt);
                base = __shfl_sync(FULL, base, 0);
                if (keep) {
                    unsigned p = base + __popc(bal & ((1u << lane) - 1u));
                    if (p < CAP) sk[p] = key;
                }
            }
        }
    }
    __syncthreads();

    // --- phase D: register bitonic sort, descending (1 key/thread, t<512) ---
    unsigned long long key = (t < CAP) ? sk[t] : 0ULL;
    for (int k = 2; k <= CAP; k <<= 1) {
        for (int j = k >> 1; j > 0; j >>= 1) {
            unsigned long long other;
            if (j >= 32) {
                if (t < CAP) sk[t] = key;
                __syncthreads();
                other = (t < CAP) ? sk[t ^ j] : key;
                __syncthreads();
            } else {
                other = __shfl_xor_sync(FULL, key, j);
            }
            bool keepMax = (((t & j) == 0) == ((t & k) == 0));
            if (keepMax ? (other > key) : (other < key)) key = other;
        }
    }
    unsigned m = min(s_cnt, (unsigned)CAP);   // m < 384 guaranteed
    if (t < CAP) {
        unsigned idx = ~(unsigned)key;
        pos[t] = make_float2((float)(idx & (S - 1)), (float)(idx >> 10));
    }
    // zero conflict matrix + init MIS state
    for (int i = t; i < 384 * MPAD; i += 1024) s_mtx[i] = 0u;
    {
        unsigned alive = __ballot_sync(FULL, t < (int)m);
        if (t < NW2 * 32 && lane == 0) { s_und[t >> 5] = alive; s_acc[t >> 5] = 0u; }
        if (t == 0) s_flag = 1;
    }
    __syncthreads();

    // --- phase E1: split-build triangular conflict matrix (2 thr/candidate) -
    {
        int i   = (t < 384) ? t : t - 384;
        int par = (t < 384) ? 0 : 1;
        if (t < 768 && i < (int)m) {
            float2 p = pos[i];
            int wi = i >> 5;
            int li = i & 31;
            for (int w = par; w <= wi; w += 2) {
                int jmax = (w == wi) ? li : 32;
                unsigned mw = 0u;
                for (int l = 0; l < jmax; l++) {
                    float2 q = pos[w * 32 + l];   // broadcast LDS
                    float dx = p.x - q.x, dy = p.y - q.y;
                    if (dx * dx + dy * dy <= 100.0f) mw |= 1u << l;
                }
                if (mw) s_mtx[i * MPAD + w] = mw;
            }
        }
    }
    __syncthreads();

    // --- phase E2: block-parallel lexicographic MIS (== greedy NMS) ---------
    float2 myp = (t < (int)m) ? pos[t] : make_float2(0.f, 0.f);
    int wi = t >> 5;
    unsigned msk[NW2];
    #pragma unroll
    for (int w = 0; w < NW2; w++) msk[w] = 0u;
    if (t < (int)m) {
        #pragma unroll
        for (int w = 0; w < NW2; w++) msk[w] = s_mtx[t * MPAD + w];
    }
    bool undec = (t < (int)m);
    bool isacc = false;

    for (int round = 0; round < 384; round++) {
        unsigned u[NW2], a[NW2];
        #pragma unroll
        for (int w = 0; w < NW2; w++) {
            if (w <= wi && w < NW2) { u[w] = s_und[w]; a[w] = s_acc[w]; }
            else { u[w] = 0u; a[w] = 0u; }
        }
        __syncthreads();
        if (t == 0) s_flag = 0;
        if (undec) {
            unsigned pend = 0u, accc = 0u;
            #pragma unroll
            for (int w = 0; w < NW2; w++) { pend |= msk[w] & u[w]; accc |= msk[w] & a[w]; }
            if (pend == 0u) { undec = false; isacc = (accc == 0u); }
        }
        __syncthreads();
        unsigned uw = __ballot_sync(FULL, undec);
        unsigned aw = __ballot_sync(FULL, isacc);
        if (t < NW2 * 32 && lane == 0) {
            s_und[t >> 5] = uw;
            s_acc[t >> 5] = aw;
            if (uw) s_flag = 1;
        }
        __syncthreads();
        if (!s_flag) break;
        __syncthreads();
    }

    // --- extract accepted in rank order, cap MAXR ---
    if (t < (int)m && isacc) {
        int below = 0;
        #pragma unroll
        for (int w = 0; w < NW2; w++) if (w < wi) below += __popc(s_acc[w]);
        below += __popc(s_acc[wi] & ((1u << lane) - 1u));
        if (below < MAXR) { g_selx[below] = (int)myp.x; g_sely[below] = (int)myp.y; }
    }
    if (t == 0) {
        int tot = 0;
        #pragma unroll
        for (int w = 0; w < NW2; w++) tot += __popc(s_acc[w]);
        g_nsel = min(tot, MAXR);
    }
}

// ---------------- K3: parallel emit (one block per kp channel) --------------
// out layout (9472 f32): root[256][2] | kp[256][17][2] | valid[256]
__global__ void __launch_bounds__(256) k_emit(const float* __restrict__ x,
                                              float* __restrict__ out) {
    int b = blockIdx.x;
    int t = threadIdx.x;           // 256 threads = one root each
    int ns = g_nsel;
    const float Z = 1.41421356237309515f * 1024.0f;  // sqrt(2)*S

    if (b < NKP) {
        int r = t;
        float kx = 0.0f, ky = 0.0f;
        if (r < ns) {
            int xi = g_selx[r], yi = g_sely[r];
            int off = yi * S + xi;
            float dxv = x[(1 + 2 * b) * SS + off];
            float dyv = x[(2 + 2 * b) * SS + off];
            float ddx = tanhf(dxv) * Z, ddy = tanhf(dyv) * Z;
            kx = ddx + (float)xi;
            ky = ddy + (float)yi;
            float d = sqrtf(ddx * ddx + ddy * ddy);
            if (d < 2.0f) { kx = 0.0f; ky = 0.0f; }
            kx *= 4.0f; ky *= 4.0f;
        }
        int j = r * NKP + b;
        out[2 * MAXR + 2 * j]     = kx;
        out[2 * MAXR + 2 * j + 1] = ky;
    } else {
        // roots + valid + scratch cleanup for next replay
        int r = t;
        bool v = (r < ns);
        float fx = v ? (float)g_selx[r] : 0.0f;
        float fy = v ? (float)g_sely[r] : 0.0f;
        out[2 * r]     = fx * 4.0f;
        out[2 * r + 1] = fy * 4.0f;
        out[2 * MAXR + MAXR * 2 * NKP + r] = v ? 1.0f : 0.0f;
        for (int h = t; h < NBH; h += 256) g_hist[h] = 0u;
        if (t == 0) g_cnt_hot = 0u;
    }
}

// ---------------- entry ----------------
extern "C" void kernel_launch(void* const* d_in, const int* in_sizes, int n_in,
                              void* d_out, int out_size) {
    const float* x = (const float*)d_in[0];
    float* out = (float*)d_out;
    (void)in_sizes; (void)n_in; (void)out_size;

    k_scan<<<SS / 4 / 512, 512>>>(x);
    k_mid<<<1, 1024>>>();
    k_emit<<<NKP + 1, 256>>>(x, out);
}

// round 11
// speedup vs baseline: 1.8151x; 1.0179x over previous
#include <cuda_runtime.h>
#include <math.h>
#include <stdint.h>

#define S 1024
#define SS (S*S)
#define NBH 4096
#define CAP 512
#define TARGETN 384u
#define MAXR 256
#define NKP 17
#define HOTCAP 8192
#define NW2 12              // 384/32 bitset words for MIS
#define MPAD 13             // padded row stride (bank-conflict-free)
#define FULL 0xFFFFFFFFu

#define HOTB  0x3F733333u   // __float_as_uint(0.95f)
#define HRNG  (0x3F800000u - 0x3F733333u)

// ---------------- scratch (static __device__, zero at module load) ----------
__device__ unsigned int       g_hist[NBH];
__device__ unsigned int       g_cnt_hot;
__device__ unsigned long long g_hot[HOTCAP];   // hot candidates (bits<<32 | ~idx)
__device__ int                g_selx[MAXR], g_sely[MAXR];
__device__ int                g_nsel;

static __device__ __forceinline__ unsigned bucket_hot(unsigned bits) {
    unsigned d = bits - HOTB;
    unsigned b = (unsigned)(((unsigned long long)d * NBH) / HRNG);
    return b >= NBH ? (NBH - 1) : b;
}

// ---------------- K1: scan heatmap; keep only conf>=0.95 candidates ---------
// 2 x float4 per thread (MLP=2), warp early-out when no candidates.
__global__ void __launch_bounds__(512) k_scan(const float* __restrict__ x) {
    const float4* __restrict__ x4 = (const float4*)x;
    int i = blockIdx.x * blockDim.x + threadIdx.x;   // SS/8 threads
    int lane = threadIdx.x & 31;

    float4 a0 = x4[i];
    float4 a1 = x4[i + SS / 8];
    float vs[8] = {a0.x, a0.y, a0.z, a0.w, a1.x, a1.y, a1.z, a1.w};

    unsigned long long keys[8];
    unsigned bbits[8];
    int cnt = 0;
    #pragma unroll
    for (int c = 0; c < 8; c++) {
        float v = vs[c];
        if (v > 2.9f) {  // prefilter; exact test on conf bits below
            float conf = 1.0f / (1.0f + expf(-v));   // same formula as reference
            unsigned bits = __float_as_uint(conf);
            if (bits >= HOTB) {
                int idx = (c < 4) ? (4 * i + c) : (4 * (i + SS / 8) + (c - 4));
                keys[cnt]  = ((unsigned long long)bits << 32) | (unsigned)(~idx);
                bbits[cnt] = bits;
                cnt++;
            }
        }
    }
    if (__ballot_sync(FULL, cnt) == 0u) return;   // ~99% of warps exit here

    unsigned pre = (unsigned)cnt;
    #pragma unroll
    for (int off = 1; off < 32; off <<= 1) {
        unsigned v = __shfl_up_sync(FULL, pre, off);
        if (lane >= off) pre += v;
    }
    unsigned total = __shfl_sync(FULL, pre, 31);
    unsigned base = 0;
    if (lane == 31) base = atomicAdd(&g_cnt_hot, total);
    base = __shfl_sync(FULL, base, 31);
    unsigned mybase = base + pre - (unsigned)cnt;
    for (int c = 0; c < cnt; c++) {
        unsigned p = mybase + c;
        if (p < HOTCAP) g_hot[p] = keys[c];
        atomicAdd(&g_hist[bucket_hot(bbits[c])], 1u);   // RED
    }
}

// ---------------- K2: cutoff + collect + reg-sort + build + pingpong-MIS ----
__global__ void __launch_bounds__(1024, 1) k_mid() {
    __shared__ unsigned long long sk[CAP];          // 4 KB (buffer A)
    __shared__ unsigned long long sk2[CAP];         // 4 KB (buffer B)
    __shared__ float2  pos[CAP];                    // 4 KB
    __shared__ unsigned s_mtx[384 * MPAD];          // ~19.5 KB conflict matrix
    __shared__ unsigned cs[1024];
    __shared__ unsigned seg_suf[32];
    __shared__ unsigned s_cut;
    __shared__ unsigned s_cnt;
    __shared__ unsigned s_und[2][NW2], s_acc[2][NW2];

    int t = threadIdx.x;
    int lane = t & 31;

    // --- phase A: per-4-bucket partial sums + init ---
    {
        unsigned s = 0;
        #pragma unroll
        for (int b = 0; b < 4; b++) s += g_hist[t * 4 + b];
        cs[t] = s;
        if (t == 0) s_cnt = 0u;
        if (t < CAP) sk[t] = 0ULL;
    }
    __syncthreads();

    // --- phase B: parallel cutoff; strictly above boundary bucket ---
    if (t < 32) {
        unsigned a = 0;
        #pragma unroll
        for (int b = 0; b < 32; b++) a += cs[lane * 32 + b];
        unsigned suf = a;
        #pragma unroll
        for (int off = 1; off < 32; off <<= 1) {
            unsigned v = __shfl_down_sync(FULL, suf, off);
            if (lane + off < 32) suf += v;
        }
        seg_suf[lane] = suf;
        __syncwarp(FULL);
        unsigned bal = __ballot_sync(FULL, suf >= TARGETN);
        if (lane == 0) {
            if (bal == 0u) { s_cut = 0u; }  // total hot < TARGETN: keep all (<384)
            else {
                int lseg = 31 - __clz(bal);
                unsigned base = (lseg < 31) ? seg_suf[lseg + 1] : 0u;
                unsigned cum = base;
                int ccut = lseg * 32;
                for (int c = lseg * 32 + 31; c >= lseg * 32; c--) {
                    cum += cs[c];
                    if (cum >= TARGETN) { ccut = c; break; }
                }
                unsigned cc = cum - cs[ccut];
                unsigned h[4];
                #pragma unroll
                for (int b = 0; b < 4; b++) h[b] = g_hist[ccut * 4 + b];
                int bcut = ccut * 4;
                #pragma unroll
                for (int b = 3; b >= 0; b--) {
                    cc += h[b];
                    if (cc >= TARGETN) { bcut = ccut * 4 + b; break; }
                }
                s_cut = (unsigned)bcut + 1u;  // strict-above => count < TARGETN
            }
        }
    }
    __syncthreads();

    // --- phase C: collect above cutoff (warp-aggregated smem append) --------
    {
        unsigned n = min(g_cnt_hot, (unsigned)HOTCAP);
        unsigned cut = s_cut;
        unsigned rounds = (n + 1023u) / 1024u;
        for (unsigned r = 0; r < rounds; r++) {
            unsigned i = r * 1024u + (unsigned)t;
            bool keep = false;
            unsigned long long key = 0ULL;
            if (i < n) {
                key = g_hot[i];
                keep = bucket_hot((unsigned)(key >> 32)) >= cut;
            }
            unsigned bal = __ballot_sync(FULL, keep);
            if (bal) {
                unsigned wcnt = __popc(bal);
                unsigned base = 0;
                if (lane == 0) base = atomicAdd(&s_cnt, wcnt);
                base = __shfl_sync(FULL, base, 0);
                if (keep) {
                    unsigned p = base + __popc(bal & ((1u << lane) - 1u));
                    if (p < CAP) sk[p] = key;
                }
            }
        }
    }
    __syncthreads();

    // --- phase D: register bitonic sort desc, ping-pong smem (1 bar/stage) --
    unsigned long long key = (t < CAP) ? sk[t] : 0ULL;
    {
        int pp = 0;   // 0 -> write sk, 1 -> write sk2
        for (int k = 2; k <= CAP; k <<= 1) {
            for (int j = k >> 1; j > 0; j >>= 1) {
                unsigned long long other;
                if (j >= 32) {
                    unsigned long long* wbuf = pp ? sk2 : sk;
                    if (t < CAP) wbuf[t] = key;
                    __syncthreads();
                    other = (t < CAP) ? wbuf[t ^ j] : key;
                    pp ^= 1;
                } else {
                    other = __shfl_xor_sync(FULL, key, j);
                }
                bool keepMax = (((t & j) == 0) == ((t & k) == 0));
                if (keepMax ? (other > key) : (other < key)) key = other;
            }
        }
    }
    unsigned m = min(s_cnt, (unsigned)CAP);   // m < 384 guaranteed
    if (t < CAP) {
        unsigned idx = ~(unsigned)key;
        pos[t] = make_float2((float)(idx & (S - 1)), (float)(idx >> 10));
    }
    // zero conflict matrix + init MIS state (buffer 0)
    for (int i = t; i < 384 * MPAD; i += 1024) s_mtx[i] = 0u;
    {
        unsigned alive = __ballot_sync(FULL, t < (int)m);
        if (t < NW2 * 32 && lane == 0) { s_und[0][t >> 5] = alive; s_acc[0][t >> 5] = 0u; }
    }
    __syncthreads();

    // --- phase E1: split-build triangular conflict matrix (2 thr/candidate) -
    {
        int i   = (t < 384) ? t : t - 384;
        int par = (t < 384) ? 0 : 1;
        if (t < 768 && i < (int)m) {
            float2 p = pos[i];
            int wi2 = i >> 5;
            int li = i & 31;
            for (int w = par; w <= wi2; w += 2) {
                int jmax = (w == wi2) ? li : 32;
                unsigned mw = 0u;
                for (int l = 0; l < jmax; l++) {
                    float2 q = pos[w * 32 + l];   // broadcast LDS
                    float dx = p.x - q.x, dy = p.y - q.y;
                    if (dx * dx + dy * dy <= 100.0f) mw |= 1u << l;
                }
                if (mw) s_mtx[i * MPAD + w] = mw;
            }
        }
    }
    __syncthreads();

    // --- phase E2: lexicographic MIS, 1 barrier per round (ping-pong) -------
    float2 myp = (t < (int)m) ? pos[t] : make_float2(0.f, 0.f);
    int wi = t >> 5;
    unsigned msk[NW2];
    #pragma unroll
    for (int w = 0; w < NW2; w++) msk[w] = 0u;
    if (t < (int)m) {
        #pragma unroll
        for (int w = 0; w < NW2; w++) msk[w] = s_mtx[t * MPAD + w];
    }
    bool undec = (t < (int)m);
    bool isacc = false;
    int cur = 0;

    for (int round = 0; round < 384; round++) {
        // snapshot (broadcast LDS) + uniform termination check
        unsigned u[NW2], a[NW2], u_all = 0u;
        #pragma unroll
        for (int w = 0; w < NW2; w++) {
            u[w] = s_und[cur][w];
            a[w] = s_acc[cur][w];
            u_all |= u[w];
        }
        if (u_all == 0u) break;          // uniform: same smem seen by all
        if (undec) {
            unsigned pend = 0u, accc = 0u;
            #pragma unroll
            for (int w = 0; w < NW2; w++) { pend |= msk[w] & u[w]; accc |= msk[w] & a[w]; }
            if (pend == 0u) { undec = false; isacc = (accc == 0u); }
        }
        unsigned uw = __ballot_sync(FULL, undec);
        unsigned aw = __ballot_sync(FULL, isacc);
        if (t < NW2 * 32 && lane == 0) {
            s_und[cur ^ 1][t >> 5] = uw;
            s_acc[cur ^ 1][t >> 5] = aw;
        }
        __syncthreads();
        cur ^= 1;
    }

    // --- extract accepted in rank order, cap MAXR ---
    if (t < (int)m && isacc) {
        int below = 0;
        #pragma unroll
        for (int w = 0; w < NW2; w++) if (w < wi) below += __popc(s_acc[cur][w]);
        below += __popc(s_acc[cur][wi] & ((1u << lane) - 1u));
        if (below < MAXR) { g_selx[below] = (int)myp.x; g_sely[below] = (int)myp.y; }
    }
    if (t == 0) {
        int tot = 0;
        #pragma unroll
        for (int w = 0; w < NW2; w++) tot += __popc(s_acc[cur][w]);
        g_nsel = min(tot, MAXR);
    }
}

// ---------------- K3: parallel emit (one block per kp channel) --------------
// out layout (9472 f32): root[256][2] | kp[256][17][2] | valid[256]
__global__ void __launch_bounds__(256) k_emit(const float* __restrict__ x,
                                              float* __restrict__ out) {
    int b = blockIdx.x;
    int t = threadIdx.x;           // 256 threads = one root each
    int ns = g_nsel;
    const float Z = 1.41421356237309515f * 1024.0f;  // sqrt(2)*S

    if (b < NKP) {
        int r = t;
        float kx = 0.0f, ky = 0.0f;
        if (r < ns) {
            int xi = g_selx[r], yi = g_sely[r];
            int off = yi * S + xi;
            float dxv = x[(1 + 2 * b) * SS + off];
            float dyv = x[(2 + 2 * b) * SS + off];
            float ddx = tanhf(dxv) * Z, ddy = tanhf(dyv) * Z;
            kx = ddx + (float)xi;
            ky = ddy + (float)yi;
            float d = sqrtf(ddx * ddx + ddy * ddy);
            if (d < 2.0f) { kx = 0.0f; ky = 0.0f; }
            kx *= 4.0f; ky *= 4.0f;
        }
        int j = r * NKP + b;
        out[2 * MAXR + 2 * j]     = kx;
        out[2 * MAXR + 2 * j + 1] = ky;
    } else {
        // roots + valid + scratch cleanup for next replay
        int r = t;
        bool v = (r < ns);
        float fx = v ? (float)g_selx[r] : 0.0f;
        float fy = v ? (float)g_sely[r] : 0.0f;
        out[2 * r]     = fx * 4.0f;
        out[2 * r + 1] = fy * 4.0f;
        out[2 * MAXR + MAXR * 2 * NKP + r] = v ? 1.0f : 0.0f;
        for (int h = t; h < NBH; h += 256) g_hist[h] = 0u;
        if (t == 0) g_cnt_hot = 0u;
    }
}

// ---------------- entry ----------------
extern "C" void kernel_launch(void* const* d_in, const int* in_sizes, int n_in,
                              void* d_out, int out_size) {
    const float* x = (const float*)d_in[0];
    float* out = (float*)d_out;
    (void)in_sizes; (void)n_in; (void)out_size;

    k_scan<<<SS / 8 / 512, 512>>>(x);
    k_mid<<<1, 1024>>>();
    k_emit<<<NKP + 1, 256>>>(x, out);
}